// round 4
// baseline (speedup 1.0000x reference)
#include <cuda_runtime.h>
#include <cuda_bf16.h>

// GCN_26817775797032: 3-layer GCN, N=50000 nodes, E=640000 edges,
// dims 256 -> 128 -> 128 -> 16.
//
// Pipeline per launch (all graph-capturable, no allocs):
//  0. detect edge_index dtype (int32 vs int64) on-device  [JAX x64-off => int32]
//  1. zero deg
//  2. count in-degrees (int atomics over dst)
//  3. single-block prefix scan -> rowstart/cursor, dis = rsqrt(1+deg)
//  4. CSR fill (scatter src ids by dst)
//  5. L1: G = (x @ W1) * dis[row]   (fp32 tiled GEMM, epilogue-fused norm)
//     AGG: H = relu(dis[i]*(G[i] + sum_{dst=i} G[src]) + b1)   (CSR gather, no atomics)
//  6. L2: same with W2 (K=128)
//  7. L3: G16 = (H @ W3) * dis[row]  (N=16 GEMM)
//     AGG16: out = dis[i]*(G16[i] + sum G16[src]) + b3   (no relu)

#define NN 50000
#define NE 640000
#define HID 128
#define NCLS 16

// ---------------- device scratch (no allocs allowed) ----------------
__device__ int   g_is64;
__device__ int   g_deg[NN];
__device__ int   g_rowstart[NN + 1];
__device__ int   g_cursor[NN];
__device__ int   g_csr[NE];
__device__ float g_dis[NN];
__device__ float g_G[(size_t)NN * HID];   // per-layer g = (A@W)*dis ; also 16-wide for layer 3
__device__ float g_H[(size_t)NN * HID];   // layer activations

// ---------------- helpers ----------------
__device__ __forceinline__ float4 f4add(float4 a, float4 b) {
    a.x += b.x; a.y += b.y; a.z += b.z; a.w += b.w; return a;
}

// Load edge-index element i (element index in [0, 2*NE)), dtype-dispatched.
__device__ __forceinline__ int load_idx(const void* __restrict__ ei, int i) {
    if (g_is64) return (int)((const long long*)ei)[i];
    return ((const int*)ei)[i];
}

// ---------------- dtype detection ----------------
// If the buffer is int64, the first 16 int64 words are valid node ids in [0, NN).
// If it is int32, each int64-read packs two ids; any nonzero high half fails the
// range check (probability of false positive ~ (1/NN)^16 ~ 0).
__global__ void detect_kernel(const void* __restrict__ ei) {
    const long long* p = (const long long*)ei;
    int ok = 1;
    for (int i = 0; i < 16; i++) {
        long long v = p[i];
        if (v < 0 || v >= NN) ok = 0;
    }
    g_is64 = ok;
}

// ---------------- preprocessing ----------------
__global__ void zero_deg_kernel() {
    int i = blockIdx.x * blockDim.x + threadIdx.x;
    if (i < NN) g_deg[i] = 0;
}

__global__ void deg_kernel(const void* __restrict__ ei) {
    int e = blockIdx.x * blockDim.x + threadIdx.x;
    if (e < NE) {
        int d = load_idx(ei, NE + e);
        if (d >= 0 && d < NN) atomicAdd(&g_deg[d], 1);
    }
}

// Single block, 1024 threads: prefix sum over 50000 degrees + dis computation.
__global__ void prefix_kernel() {
    __shared__ int ps[1024];
    const int CH = (NN + 1023) / 1024;  // 49
    int t = threadIdx.x;
    int b = t * CH;
    int e = b + CH; if (e > NN) e = NN;
    if (b > NN) b = NN;

    int s = 0;
    for (int i = b; i < e; i++) s += g_deg[i];
    ps[t] = s;
    __syncthreads();

    // inclusive Hillis-Steele scan
    for (int d = 1; d < 1024; d <<= 1) {
        int v = (t >= d) ? ps[t - d] : 0;
        __syncthreads();
        ps[t] += v;
        __syncthreads();
    }

    int off = (t == 0) ? 0 : ps[t - 1];
    for (int i = b; i < e; i++) {
        g_rowstart[i] = off;
        g_cursor[i]   = off;
        off += g_deg[i];
        g_dis[i] = rsqrtf(1.0f + (float)g_deg[i]);   // +1 self-loop
    }
    if (t == 1023) g_rowstart[NN] = ps[1023];
}

__global__ void fill_kernel(const void* __restrict__ ei) {
    int e = blockIdx.x * blockDim.x + threadIdx.x;
    if (e < NE) {
        int s = load_idx(ei, e);
        int d = load_idx(ei, NE + e);
        if (s >= 0 && s < NN && d >= 0 && d < NN) {
            int pos = atomicAdd(&g_cursor[d], 1);
            if (pos >= 0 && pos < NE) g_csr[pos] = s;
        }
    }
}

// ---------------- GEMM: [NN x K] @ [K x 128], out = result * dis[row] -> g_G ----------------
// BM=128, BN=128, BK=16, 256 threads, 8x8 thread tile.
__global__ __launch_bounds__(256) void gemm128_kernel(
    const float* __restrict__ Aext, const float* __restrict__ W, int K, int srcH)
{
    const float* __restrict__ A = srcH ? g_H : Aext;
    __shared__ float As[16][136];   // [k][m], padded
    __shared__ float Bs[16][128];   // [k][n]

    int tid = threadIdx.x;
    int m0  = blockIdx.x * 128;
    int tx  = tid & 15;    // col group
    int ty  = tid >> 4;    // row group

    float acc[8][8];
#pragma unroll
    for (int r = 0; r < 8; r++)
#pragma unroll
        for (int c = 0; c < 8; c++) acc[r][c] = 0.0f;

    for (int k0 = 0; k0 < K; k0 += 16) {
        // Load A tile 128x16 (512 float4, 2 per thread), store transposed.
#pragma unroll
        for (int i = 0; i < 2; i++) {
            int l   = tid * 2 + i;
            int row = l >> 2;
            int kc  = (l & 3) << 2;
            int gr  = m0 + row;
            float4 v = make_float4(0.f, 0.f, 0.f, 0.f);
            if (gr < NN) v = *(const float4*)(A + (size_t)gr * K + k0 + kc);
            As[kc + 0][row] = v.x;
            As[kc + 1][row] = v.y;
            As[kc + 2][row] = v.z;
            As[kc + 3][row] = v.w;
        }
        // Load B tile 16x128 (512 float4, 2 per thread).
#pragma unroll
        for (int i = 0; i < 2; i++) {
            int l  = tid * 2 + i;
            int kr = l >> 5;
            int nc = (l & 31) << 2;
            *(float4*)&Bs[kr][nc] = *(const float4*)(W + (size_t)(k0 + kr) * 128 + nc);
        }
        __syncthreads();

#pragma unroll
        for (int k = 0; k < 16; k++) {
            float a[8], bb[8];
            float4 a0 = *(const float4*)&As[k][ty * 8];
            float4 a1 = *(const float4*)&As[k][ty * 8 + 4];
            a[0]=a0.x; a[1]=a0.y; a[2]=a0.z; a[3]=a0.w;
            a[4]=a1.x; a[5]=a1.y; a[6]=a1.z; a[7]=a1.w;
            float4 b0 = *(const float4*)&Bs[k][tx * 8];
            float4 b1 = *(const float4*)&Bs[k][tx * 8 + 4];
            bb[0]=b0.x; bb[1]=b0.y; bb[2]=b0.z; bb[3]=b0.w;
            bb[4]=b1.x; bb[5]=b1.y; bb[6]=b1.z; bb[7]=b1.w;
#pragma unroll
            for (int r = 0; r < 8; r++)
#pragma unroll
                for (int c = 0; c < 8; c++)
                    acc[r][c] += a[r] * bb[c];
        }
        __syncthreads();
    }

#pragma unroll
    for (int r = 0; r < 8; r++) {
        int gr = m0 + ty * 8 + r;
        if (gr < NN) {
            float d = g_dis[gr];
            float4 v0 = make_float4(acc[r][0]*d, acc[r][1]*d, acc[r][2]*d, acc[r][3]*d);
            float4 v1 = make_float4(acc[r][4]*d, acc[r][5]*d, acc[r][6]*d, acc[r][7]*d);
            *(float4*)(g_G + (size_t)gr * 128 + tx * 8)     = v0;
            *(float4*)(g_G + (size_t)gr * 128 + tx * 8 + 4) = v1;
        }
    }
}

// ---------------- GEMM: [NN x 128] @ [128 x 16], out = result * dis[row] -> g_G ----------------
// BM=512, BK=16, 256 threads; thread tile 4 rows x 8 cols.
__global__ __launch_bounds__(256) void gemm16_kernel(const float* __restrict__ W3)
{
    __shared__ float As[16][520];  // [k][m], padded (row stride 2080B, 16B-aligned)
    __shared__ float Bs[16][16];

    int tid = threadIdx.x;
    int m0  = blockIdx.x * 512;
    int tx  = tid & 1;     // col group (8 cols each)
    int ty  = tid >> 1;    // row group (4 rows each), 0..127

    float acc[4][8];
#pragma unroll
    for (int r = 0; r < 4; r++)
#pragma unroll
        for (int c = 0; c < 8; c++) acc[r][c] = 0.0f;

    for (int k0 = 0; k0 < 128; k0 += 16) {
        // A tile: 512 rows x 16 k = 2048 float4, 8 per thread
#pragma unroll
        for (int i = 0; i < 8; i++) {
            int l   = i * 256 + tid;
            int row = l >> 2;
            int kc  = (l & 3) << 2;
            int gr  = m0 + row;
            float4 v = make_float4(0.f, 0.f, 0.f, 0.f);
            if (gr < NN) v = *(const float4*)(g_H + (size_t)gr * 128 + k0 + kc);
            As[kc + 0][row] = v.x;
            As[kc + 1][row] = v.y;
            As[kc + 2][row] = v.z;
            As[kc + 3][row] = v.w;
        }
        // B tile: 16x16 = 64 float4
        if (tid < 64) {
            int kr = tid >> 2;
            int nc = (tid & 3) << 2;
            *(float4*)&Bs[kr][nc] = *(const float4*)(W3 + (size_t)(k0 + kr) * 16 + nc);
        }
        __syncthreads();

#pragma unroll
        for (int k = 0; k < 16; k++) {
            float4 av = *(const float4*)&As[k][ty * 4];
            float a[4] = {av.x, av.y, av.z, av.w};
            float4 b0 = *(const float4*)&Bs[k][tx * 8];
            float4 b1 = *(const float4*)&Bs[k][tx * 8 + 4];
            float bb[8] = {b0.x,b0.y,b0.z,b0.w,b1.x,b1.y,b1.z,b1.w};
#pragma unroll
            for (int r = 0; r < 4; r++)
#pragma unroll
                for (int c = 0; c < 8; c++)
                    acc[r][c] += a[r] * bb[c];
        }
        __syncthreads();
    }

#pragma unroll
    for (int r = 0; r < 4; r++) {
        int gr = m0 + ty * 4 + r;
        if (gr < NN) {
            float d = g_dis[gr];
            float4 v0 = make_float4(acc[r][0]*d, acc[r][1]*d, acc[r][2]*d, acc[r][3]*d);
            float4 v1 = make_float4(acc[r][4]*d, acc[r][5]*d, acc[r][6]*d, acc[r][7]*d);
            *(float4*)(g_G + (size_t)gr * 16 + tx * 8)     = v0;
            *(float4*)(g_G + (size_t)gr * 16 + tx * 8 + 4) = v1;
        }
    }
}

// ---------------- Aggregation (128-wide): H = relu(dis[i]*(G[i] + sum G[src]) + b) ----------------
// One warp per node; lane l handles float4 #l of the 128-float row.
__global__ __launch_bounds__(256) void agg128_kernel(const float* __restrict__ bias)
{
    int gt   = blockIdx.x * blockDim.x + threadIdx.x;
    int node = gt >> 5;
    int lane = gt & 31;
    if (node >= NN) return;

    const float4* __restrict__ Gv = (const float4*)g_G;
    float4 acc = Gv[(size_t)node * 32 + lane];   // self-loop term

    int s0 = g_rowstart[node];
    int s1 = g_rowstart[node + 1];
    for (int j = s0; j < s1; j++) {
        int s = g_csr[j];
        acc = f4add(acc, Gv[(size_t)s * 32 + lane]);
    }

    float d = g_dis[node];
    float4 b = ((const float4*)bias)[lane];
    float4 r;
    r.x = fmaxf(acc.x * d + b.x, 0.0f);
    r.y = fmaxf(acc.y * d + b.y, 0.0f);
    r.z = fmaxf(acc.z * d + b.z, 0.0f);
    r.w = fmaxf(acc.w * d + b.w, 0.0f);
    ((float4*)g_H)[(size_t)node * 32 + lane] = r;
}

// ---------------- Aggregation (16-wide, final): out = dis[i]*(G[i] + sum G[src]) + b ----------------
// 4 threads per node, float4 each.
__global__ __launch_bounds__(256) void agg16_kernel(const float* __restrict__ bias,
                                                    float* __restrict__ out)
{
    int gt   = blockIdx.x * blockDim.x + threadIdx.x;
    int node = gt >> 2;
    int q    = gt & 3;
    if (node >= NN) return;

    const float4* __restrict__ Gv = (const float4*)g_G;
    float4 acc = Gv[(size_t)node * 4 + q];

    int s0 = g_rowstart[node];
    int s1 = g_rowstart[node + 1];
    for (int j = s0; j < s1; j++) {
        int s = g_csr[j];
        acc = f4add(acc, Gv[(size_t)s * 4 + q]);
    }

    float d = g_dis[node];
    float4 b = ((const float4*)bias)[q];
    float4 r;
    r.x = acc.x * d + b.x;
    r.y = acc.y * d + b.y;
    r.z = acc.z * d + b.z;
    r.w = acc.w * d + b.w;
    ((float4*)out)[(size_t)node * 4 + q] = r;
}

// ---------------- launch ----------------
extern "C" void kernel_launch(void* const* d_in, const int* in_sizes, int n_in,
                              void* d_out, int out_size)
{
    const float* x  = (const float*)d_in[0];
    const void*  ei = d_in[1];                 // int32 or int64, detected on device
    const float* W1 = (const float*)d_in[2];
    const float* b1 = (const float*)d_in[3];
    const float* W2 = (const float*)d_in[4];
    const float* b2 = (const float*)d_in[5];
    const float* W3 = (const float*)d_in[6];
    const float* b3 = (const float*)d_in[7];
    float* out = (float*)d_out;

    // preprocessing: dtype detect -> degrees -> prefix/dis -> CSR
    detect_kernel<<<1, 1>>>(ei);
    zero_deg_kernel<<<(NN + 255) / 256, 256>>>();
    deg_kernel<<<(NE + 255) / 256, 256>>>(ei);
    prefix_kernel<<<1, 1024>>>();
    fill_kernel<<<(NE + 255) / 256, 256>>>(ei);

    const int gemm_blocks   = (NN + 127) / 128;        // 391
    const int agg128_blocks = (NN * 32 + 255) / 256;   // 6250
    const int agg16_blocks  = (NN * 4 + 255) / 256;    // 782
    const int gemm16_blocks = (NN + 511) / 512;        // 98

    // Layer 1: K=256
    gemm128_kernel<<<gemm_blocks, 256>>>(x, W1, 256, 0);
    agg128_kernel<<<agg128_blocks, 256>>>(b1);

    // Layer 2: K=128
    gemm128_kernel<<<gemm_blocks, 256>>>(nullptr, W2, 128, 1);
    agg128_kernel<<<agg128_blocks, 256>>>(b2);

    // Layer 3: 128 -> 16, no relu
    gemm16_kernel<<<gemm16_blocks, 256>>>(W3);
    agg16_kernel<<<agg16_blocks, 256>>>(b3, out);
}

// round 5
// speedup vs baseline: 1.3486x; 1.3486x over previous
#include <cuda_runtime.h>
#include <cuda_bf16.h>

// GCN_26817775797032: 3-layer GCN, N=50000 nodes, E=640000 edges,
// dims 256 -> 128 -> 128 -> 16.
//
// R5: replace the single-block prefix scan (103.8us, issue=4%, 1 SM busy)
// with a chip-wide 3-kernel hierarchical scan (predicted <=8us total).

#define NN 50000
#define NE 640000
#define HID 128
#define NCLS 16
#define NT4 12500           // NN/4, exact
#define SCAN_BLOCKS 49      // ceil(12500/256)

// ---------------- device scratch (no allocs allowed) ----------------
__device__ int   g_is64;
__device__ __align__(16) int g_deg[NN];
__device__ int   g_rowstart[NN + 1];
__device__ int   g_cursor[NN];
__device__ int   g_csr[NE];
__device__ float g_dis[NN];
__device__ int   g_blocksum[SCAN_BLOCKS];
__device__ int   g_blockoff[SCAN_BLOCKS];
__device__ float g_G[(size_t)NN * HID];   // per-layer g = (A@W)*dis ; also 16-wide for layer 3
__device__ float g_H[(size_t)NN * HID];   // layer activations

// ---------------- helpers ----------------
__device__ __forceinline__ float4 f4add(float4 a, float4 b) {
    a.x += b.x; a.y += b.y; a.z += b.z; a.w += b.w; return a;
}

// Load edge-index element i (element index in [0, 2*NE)), dtype-dispatched.
__device__ __forceinline__ int load_idx(const void* __restrict__ ei, int i) {
    if (g_is64) return (int)((const long long*)ei)[i];
    return ((const int*)ei)[i];
}

// ---------------- dtype detection (one warp) ----------------
// If the buffer is int64, the first 32 int64 words are valid node ids in [0, NN).
// If it is int32, each int64-read packs two ids; any nonzero high half fails the
// range check (false-positive probability ~ (1/NN)^32 ~ 0).
__global__ void detect_kernel(const void* __restrict__ ei) {
    const long long* p = (const long long*)ei;
    long long v = p[threadIdx.x];
    unsigned bad = __ballot_sync(0xFFFFFFFFu, v < 0 || v >= NN);
    if (threadIdx.x == 0) g_is64 = (bad == 0u);
}

// ---------------- preprocessing ----------------
__global__ void zero_deg_kernel() {
    int i = blockIdx.x * blockDim.x + threadIdx.x;
    if (i < NN) g_deg[i] = 0;
}

__global__ void deg_kernel(const void* __restrict__ ei) {
    int e = blockIdx.x * blockDim.x + threadIdx.x;
    if (e < NE) {
        int d = load_idx(ei, NE + e);
        if (d >= 0 && d < NN) atomicAdd(&g_deg[d], 1);
    }
}

// ---- hierarchical scan: 49 blocks x 256 threads, 4 nodes/thread ----
__global__ __launch_bounds__(256) void scan1_kernel() {
    int t = blockIdx.x * 256 + threadIdx.x;
    int s = 0;
    if (t < NT4) {
        int4 v = ((const int4*)g_deg)[t];
        s = v.x + v.y + v.z + v.w;
    }
    __shared__ int ws[8];
#pragma unroll
    for (int o = 16; o > 0; o >>= 1) s += __shfl_down_sync(0xFFFFFFFFu, s, o);
    if ((threadIdx.x & 31) == 0) ws[threadIdx.x >> 5] = s;
    __syncthreads();
    if (threadIdx.x < 8) {
        int v = ws[threadIdx.x];
#pragma unroll
        for (int o = 4; o > 0; o >>= 1) v += __shfl_down_sync(0xFFu, v, o);
        if (threadIdx.x == 0) g_blocksum[blockIdx.x] = v;
    }
}

__global__ void scan2_kernel() {
    __shared__ int sh[64];
    int t = threadIdx.x;
    sh[t] = (t < SCAN_BLOCKS) ? g_blocksum[t] : 0;
    __syncthreads();
#pragma unroll
    for (int d = 1; d < 64; d <<= 1) {
        int v = (t >= d) ? sh[t - d] : 0;
        __syncthreads();
        sh[t] += v;
        __syncthreads();
    }
    if (t < SCAN_BLOCKS) g_blockoff[t] = (t == 0) ? 0 : sh[t - 1];
    if (t == SCAN_BLOCKS - 1) g_rowstart[NN] = sh[SCAN_BLOCKS - 1];
}

__global__ __launch_bounds__(256) void scan3_kernel() {
    int tid  = threadIdx.x;
    int lane = tid & 31;
    int warp = tid >> 5;
    int t    = blockIdx.x * 256 + tid;

    int4 v = make_int4(0, 0, 0, 0);
    if (t < NT4) v = ((const int4*)g_deg)[t];
    int s = v.x + v.y + v.z + v.w;

    // warp inclusive scan
    int inc = s;
#pragma unroll
    for (int o = 1; o < 32; o <<= 1) {
        int u = __shfl_up_sync(0xFFFFFFFFu, inc, o);
        if (lane >= o) inc += u;
    }
    __shared__ int wsum[8], woff[8];
    if (lane == 31) wsum[warp] = inc;
    __syncthreads();
    if (tid < 8) {
        int w  = wsum[tid];
        int wi = w;
#pragma unroll
        for (int o = 1; o < 8; o <<= 1) {
            int u = __shfl_up_sync(0xFFu, wi, o);
            if (tid >= o) wi += u;
        }
        woff[tid] = wi - w;   // exclusive warp offset
    }
    __syncthreads();

    if (t < NT4) {
        int off = (inc - s) + woff[warp] + g_blockoff[blockIdx.x];
        int base = t * 4;
        g_rowstart[base + 0] = off; g_cursor[base + 0] = off;
        g_dis[base + 0] = rsqrtf(1.0f + (float)v.x); off += v.x;
        g_rowstart[base + 1] = off; g_cursor[base + 1] = off;
        g_dis[base + 1] = rsqrtf(1.0f + (float)v.y); off += v.y;
        g_rowstart[base + 2] = off; g_cursor[base + 2] = off;
        g_dis[base + 2] = rsqrtf(1.0f + (float)v.z); off += v.z;
        g_rowstart[base + 3] = off; g_cursor[base + 3] = off;
        g_dis[base + 3] = rsqrtf(1.0f + (float)v.w);
    }
}

__global__ void fill_kernel(const void* __restrict__ ei) {
    int e = blockIdx.x * blockDim.x + threadIdx.x;
    if (e < NE) {
        int s = load_idx(ei, e);
        int d = load_idx(ei, NE + e);
        if (s >= 0 && s < NN && d >= 0 && d < NN) {
            int pos = atomicAdd(&g_cursor[d], 1);
            if (pos >= 0 && pos < NE) g_csr[pos] = s;
        }
    }
}

// ---------------- GEMM: [NN x K] @ [K x 128], out = result * dis[row] -> g_G ----------------
// BM=128, BN=128, BK=16, 256 threads, 8x8 thread tile.
__global__ __launch_bounds__(256) void gemm128_kernel(
    const float* __restrict__ Aext, const float* __restrict__ W, int K, int srcH)
{
    const float* __restrict__ A = srcH ? g_H : Aext;
    __shared__ float As[16][136];   // [k][m], padded
    __shared__ float Bs[16][128];   // [k][n]

    int tid = threadIdx.x;
    int m0  = blockIdx.x * 128;
    int tx  = tid & 15;    // col group
    int ty  = tid >> 4;    // row group

    float acc[8][8];
#pragma unroll
    for (int r = 0; r < 8; r++)
#pragma unroll
        for (int c = 0; c < 8; c++) acc[r][c] = 0.0f;

    for (int k0 = 0; k0 < K; k0 += 16) {
        // Load A tile 128x16 (512 float4, 2 per thread), store transposed.
#pragma unroll
        for (int i = 0; i < 2; i++) {
            int l   = tid * 2 + i;
            int row = l >> 2;
            int kc  = (l & 3) << 2;
            int gr  = m0 + row;
            float4 v = make_float4(0.f, 0.f, 0.f, 0.f);
            if (gr < NN) v = *(const float4*)(A + (size_t)gr * K + k0 + kc);
            As[kc + 0][row] = v.x;
            As[kc + 1][row] = v.y;
            As[kc + 2][row] = v.z;
            As[kc + 3][row] = v.w;
        }
        // Load B tile 16x128 (512 float4, 2 per thread).
#pragma unroll
        for (int i = 0; i < 2; i++) {
            int l  = tid * 2 + i;
            int kr = l >> 5;
            int nc = (l & 31) << 2;
            *(float4*)&Bs[kr][nc] = *(const float4*)(W + (size_t)(k0 + kr) * 128 + nc);
        }
        __syncthreads();

#pragma unroll
        for (int k = 0; k < 16; k++) {
            float a[8], bb[8];
            float4 a0 = *(const float4*)&As[k][ty * 8];
            float4 a1 = *(const float4*)&As[k][ty * 8 + 4];
            a[0]=a0.x; a[1]=a0.y; a[2]=a0.z; a[3]=a0.w;
            a[4]=a1.x; a[5]=a1.y; a[6]=a1.z; a[7]=a1.w;
            float4 b0 = *(const float4*)&Bs[k][tx * 8];
            float4 b1 = *(const float4*)&Bs[k][tx * 8 + 4];
            bb[0]=b0.x; bb[1]=b0.y; bb[2]=b0.z; bb[3]=b0.w;
            bb[4]=b1.x; bb[5]=b1.y; bb[6]=b1.z; bb[7]=b1.w;
#pragma unroll
            for (int r = 0; r < 8; r++)
#pragma unroll
                for (int c = 0; c < 8; c++)
                    acc[r][c] += a[r] * bb[c];
        }
        __syncthreads();
    }

#pragma unroll
    for (int r = 0; r < 8; r++) {
        int gr = m0 + ty * 8 + r;
        if (gr < NN) {
            float d = g_dis[gr];
            float4 v0 = make_float4(acc[r][0]*d, acc[r][1]*d, acc[r][2]*d, acc[r][3]*d);
            float4 v1 = make_float4(acc[r][4]*d, acc[r][5]*d, acc[r][6]*d, acc[r][7]*d);
            *(float4*)(g_G + (size_t)gr * 128 + tx * 8)     = v0;
            *(float4*)(g_G + (size_t)gr * 128 + tx * 8 + 4) = v1;
        }
    }
}

// ---------------- GEMM: [NN x 128] @ [128 x 16], out = result * dis[row] -> g_G ----------------
// BM=512, BK=16, 256 threads; thread tile 4 rows x 8 cols.
__global__ __launch_bounds__(256) void gemm16_kernel(const float* __restrict__ W3)
{
    __shared__ float As[16][520];  // [k][m], padded
    __shared__ float Bs[16][16];

    int tid = threadIdx.x;
    int m0  = blockIdx.x * 512;
    int tx  = tid & 1;     // col group (8 cols each)
    int ty  = tid >> 1;    // row group (4 rows each), 0..127

    float acc[4][8];
#pragma unroll
    for (int r = 0; r < 4; r++)
#pragma unroll
        for (int c = 0; c < 8; c++) acc[r][c] = 0.0f;

    for (int k0 = 0; k0 < 128; k0 += 16) {
        // A tile: 512 rows x 16 k = 2048 float4, 8 per thread
#pragma unroll
        for (int i = 0; i < 8; i++) {
            int l   = i * 256 + tid;
            int row = l >> 2;
            int kc  = (l & 3) << 2;
            int gr  = m0 + row;
            float4 v = make_float4(0.f, 0.f, 0.f, 0.f);
            if (gr < NN) v = *(const float4*)(g_H + (size_t)gr * 128 + k0 + kc);
            As[kc + 0][row] = v.x;
            As[kc + 1][row] = v.y;
            As[kc + 2][row] = v.z;
            As[kc + 3][row] = v.w;
        }
        // B tile: 16x16 = 64 float4
        if (tid < 64) {
            int kr = tid >> 2;
            int nc = (tid & 3) << 2;
            *(float4*)&Bs[kr][nc] = *(const float4*)(W3 + (size_t)(k0 + kr) * 16 + nc);
        }
        __syncthreads();

#pragma unroll
        for (int k = 0; k < 16; k++) {
            float4 av = *(const float4*)&As[k][ty * 4];
            float a[4] = {av.x, av.y, av.z, av.w};
            float4 b0 = *(const float4*)&Bs[k][tx * 8];
            float4 b1 = *(const float4*)&Bs[k][tx * 8 + 4];
            float bb[8] = {b0.x,b0.y,b0.z,b0.w,b1.x,b1.y,b1.z,b1.w};
#pragma unroll
            for (int r = 0; r < 4; r++)
#pragma unroll
                for (int c = 0; c < 8; c++)
                    acc[r][c] += a[r] * bb[c];
        }
        __syncthreads();
    }

#pragma unroll
    for (int r = 0; r < 4; r++) {
        int gr = m0 + ty * 4 + r;
        if (gr < NN) {
            float d = g_dis[gr];
            float4 v0 = make_float4(acc[r][0]*d, acc[r][1]*d, acc[r][2]*d, acc[r][3]*d);
            float4 v1 = make_float4(acc[r][4]*d, acc[r][5]*d, acc[r][6]*d, acc[r][7]*d);
            *(float4*)(g_G + (size_t)gr * 16 + tx * 8)     = v0;
            *(float4*)(g_G + (size_t)gr * 16 + tx * 8 + 4) = v1;
        }
    }
}

// ---------------- Aggregation (128-wide): H = relu(dis[i]*(G[i] + sum G[src]) + b) ----------------
// One warp per node; lane l handles float4 #l of the 128-float row.
__global__ __launch_bounds__(256) void agg128_kernel(const float* __restrict__ bias)
{
    int gt   = blockIdx.x * blockDim.x + threadIdx.x;
    int node = gt >> 5;
    int lane = gt & 31;
    if (node >= NN) return;

    const float4* __restrict__ Gv = (const float4*)g_G;
    float4 acc = Gv[(size_t)node * 32 + lane];   // self-loop term

    int s0 = g_rowstart[node];
    int s1 = g_rowstart[node + 1];
    for (int j = s0; j < s1; j++) {
        int s = g_csr[j];
        acc = f4add(acc, Gv[(size_t)s * 32 + lane]);
    }

    float d = g_dis[node];
    float4 b = ((const float4*)bias)[lane];
    float4 r;
    r.x = fmaxf(acc.x * d + b.x, 0.0f);
    r.y = fmaxf(acc.y * d + b.y, 0.0f);
    r.z = fmaxf(acc.z * d + b.z, 0.0f);
    r.w = fmaxf(acc.w * d + b.w, 0.0f);
    ((float4*)g_H)[(size_t)node * 32 + lane] = r;
}

// ---------------- Aggregation (16-wide, final): out = dis[i]*(G[i] + sum G[src]) + b ----------------
// 4 threads per node, float4 each.
__global__ __launch_bounds__(256) void agg16_kernel(const float* __restrict__ bias,
                                                    float* __restrict__ out)
{
    int gt   = blockIdx.x * blockDim.x + threadIdx.x;
    int node = gt >> 2;
    int q    = gt & 3;
    if (node >= NN) return;

    const float4* __restrict__ Gv = (const float4*)g_G;
    float4 acc = Gv[(size_t)node * 4 + q];

    int s0 = g_rowstart[node];
    int s1 = g_rowstart[node + 1];
    for (int j = s0; j < s1; j++) {
        int s = g_csr[j];
        acc = f4add(acc, Gv[(size_t)s * 4 + q]);
    }

    float d = g_dis[node];
    float4 b = ((const float4*)bias)[q];
    float4 r;
    r.x = acc.x * d + b.x;
    r.y = acc.y * d + b.y;
    r.z = acc.z * d + b.z;
    r.w = acc.w * d + b.w;
    ((float4*)out)[(size_t)node * 4 + q] = r;
}

// ---------------- launch ----------------
extern "C" void kernel_launch(void* const* d_in, const int* in_sizes, int n_in,
                              void* d_out, int out_size)
{
    const float* x  = (const float*)d_in[0];
    const void*  ei = d_in[1];                 // int32 or int64, detected on device
    const float* W1 = (const float*)d_in[2];
    const float* b1 = (const float*)d_in[3];
    const float* W2 = (const float*)d_in[4];
    const float* b2 = (const float*)d_in[5];
    const float* W3 = (const float*)d_in[6];
    const float* b3 = (const float*)d_in[7];
    float* out = (float*)d_out;

    // preprocessing: dtype detect -> degrees -> hierarchical scan -> CSR
    detect_kernel<<<1, 32>>>(ei);
    zero_deg_kernel<<<(NN + 255) / 256, 256>>>();
    deg_kernel<<<(NE + 255) / 256, 256>>>(ei);
    scan1_kernel<<<SCAN_BLOCKS, 256>>>();
    scan2_kernel<<<1, 64>>>();
    scan3_kernel<<<SCAN_BLOCKS, 256>>>();
    fill_kernel<<<(NE + 255) / 256, 256>>>(ei);

    const int gemm_blocks   = (NN + 127) / 128;        // 391
    const int agg128_blocks = (NN * 32 + 255) / 256;   // 6250
    const int agg16_blocks  = (NN * 4 + 255) / 256;    // 782
    const int gemm16_blocks = (NN + 511) / 512;        // 98

    // Layer 1: K=256
    gemm128_kernel<<<gemm_blocks, 256>>>(x, W1, 256, 0);
    agg128_kernel<<<agg128_blocks, 256>>>(b1);

    // Layer 2: K=128
    gemm128_kernel<<<gemm_blocks, 256>>>(nullptr, W2, 128, 1);
    agg128_kernel<<<agg128_blocks, 256>>>(b2);

    // Layer 3: 128 -> 16, no relu
    gemm16_kernel<<<gemm16_blocks, 256>>>(W3);
    agg16_kernel<<<agg16_blocks, 256>>>(b3, out);
}

// round 6
// speedup vs baseline: 2.1226x; 1.5739x over previous
#include <cuda_runtime.h>
#include <cuda_bf16.h>
#include <cstdint>

// GCN_26817775797032: 3-layer GCN, N=50000 nodes, E=640000 edges,
// dims 256 -> 128 -> 128 -> 16.
//
// R6: 128-wide GEMMs moved to tf32 tensor cores (mma.sync m16n8k8),
// cvt.rna rounding in smem staging, conflict-free fragment LDS (stride 136).

#define NN 50000
#define NE 640000
#define HID 128
#define NCLS 16
#define NT4 12500           // NN/4, exact
#define SCAN_BLOCKS 49      // ceil(12500/256)

// ---------------- device scratch (no allocs allowed) ----------------
__device__ int   g_is64;
__device__ __align__(16) int g_deg[NN];
__device__ int   g_rowstart[NN + 1];
__device__ int   g_cursor[NN];
__device__ int   g_csr[NE];
__device__ float g_dis[NN];
__device__ int   g_blocksum[SCAN_BLOCKS];
__device__ int   g_blockoff[SCAN_BLOCKS];
__device__ float g_G[(size_t)NN * HID];   // per-layer g = (A@W)*dis ; also 16-wide for layer 3
__device__ float g_H[(size_t)NN * HID];   // layer activations

// ---------------- helpers ----------------
__device__ __forceinline__ float4 f4add(float4 a, float4 b) {
    a.x += b.x; a.y += b.y; a.z += b.z; a.w += b.w; return a;
}

__device__ __forceinline__ uint32_t f2tf32(float f) {
    uint32_t u;
    asm("cvt.rna.tf32.f32 %0, %1;" : "=r"(u) : "f"(f));
    return u;
}

__device__ __forceinline__ void mma_tf32(float* d, const uint32_t* a, const uint32_t* b) {
    asm volatile(
        "mma.sync.aligned.m16n8k8.row.col.f32.tf32.tf32.f32 "
        "{%0,%1,%2,%3}, {%4,%5,%6,%7}, {%8,%9}, {%0,%1,%2,%3};"
        : "+f"(d[0]), "+f"(d[1]), "+f"(d[2]), "+f"(d[3])
        : "r"(a[0]), "r"(a[1]), "r"(a[2]), "r"(a[3]), "r"(b[0]), "r"(b[1]));
}

// Load edge-index element i (element index in [0, 2*NE)), dtype-dispatched.
__device__ __forceinline__ int load_idx(const void* __restrict__ ei, int i) {
    if (g_is64) return (int)((const long long*)ei)[i];
    return ((const int*)ei)[i];
}

// ---------------- dtype detection (one warp) ----------------
__global__ void detect_kernel(const void* __restrict__ ei) {
    const long long* p = (const long long*)ei;
    long long v = p[threadIdx.x];
    unsigned bad = __ballot_sync(0xFFFFFFFFu, v < 0 || v >= NN);
    if (threadIdx.x == 0) g_is64 = (bad == 0u);
}

// ---------------- preprocessing ----------------
__global__ void zero_deg_kernel() {
    int i = blockIdx.x * blockDim.x + threadIdx.x;
    if (i < NN) g_deg[i] = 0;
}

__global__ void deg_kernel(const void* __restrict__ ei) {
    int e = blockIdx.x * blockDim.x + threadIdx.x;
    if (e < NE) {
        int d = load_idx(ei, NE + e);
        if (d >= 0 && d < NN) atomicAdd(&g_deg[d], 1);
    }
}

// ---- hierarchical scan: 49 blocks x 256 threads, 4 nodes/thread ----
__global__ __launch_bounds__(256) void scan1_kernel() {
    int t = blockIdx.x * 256 + threadIdx.x;
    int s = 0;
    if (t < NT4) {
        int4 v = ((const int4*)g_deg)[t];
        s = v.x + v.y + v.z + v.w;
    }
    __shared__ int ws[8];
#pragma unroll
    for (int o = 16; o > 0; o >>= 1) s += __shfl_down_sync(0xFFFFFFFFu, s, o);
    if ((threadIdx.x & 31) == 0) ws[threadIdx.x >> 5] = s;
    __syncthreads();
    if (threadIdx.x < 8) {
        int v = ws[threadIdx.x];
#pragma unroll
        for (int o = 4; o > 0; o >>= 1) v += __shfl_down_sync(0xFFu, v, o);
        if (threadIdx.x == 0) g_blocksum[blockIdx.x] = v;
    }
}

__global__ void scan2_kernel() {
    __shared__ int sh[64];
    int t = threadIdx.x;
    sh[t] = (t < SCAN_BLOCKS) ? g_blocksum[t] : 0;
    __syncthreads();
#pragma unroll
    for (int d = 1; d < 64; d <<= 1) {
        int v = (t >= d) ? sh[t - d] : 0;
        __syncthreads();
        sh[t] += v;
        __syncthreads();
    }
    if (t < SCAN_BLOCKS) g_blockoff[t] = (t == 0) ? 0 : sh[t - 1];
    if (t == SCAN_BLOCKS - 1) g_rowstart[NN] = sh[SCAN_BLOCKS - 1];
}

__global__ __launch_bounds__(256) void scan3_kernel() {
    int tid  = threadIdx.x;
    int lane = tid & 31;
    int warp = tid >> 5;
    int t    = blockIdx.x * 256 + tid;

    int4 v = make_int4(0, 0, 0, 0);
    if (t < NT4) v = ((const int4*)g_deg)[t];
    int s = v.x + v.y + v.z + v.w;

    int inc = s;
#pragma unroll
    for (int o = 1; o < 32; o <<= 1) {
        int u = __shfl_up_sync(0xFFFFFFFFu, inc, o);
        if (lane >= o) inc += u;
    }
    __shared__ int wsum[8], woff[8];
    if (lane == 31) wsum[warp] = inc;
    __syncthreads();
    if (tid < 8) {
        int w  = wsum[tid];
        int wi = w;
#pragma unroll
        for (int o = 1; o < 8; o <<= 1) {
            int u = __shfl_up_sync(0xFFu, wi, o);
            if (tid >= o) wi += u;
        }
        woff[tid] = wi - w;
    }
    __syncthreads();

    if (t < NT4) {
        int off = (inc - s) + woff[warp] + g_blockoff[blockIdx.x];
        int base = t * 4;
        g_rowstart[base + 0] = off; g_cursor[base + 0] = off;
        g_dis[base + 0] = rsqrtf(1.0f + (float)v.x); off += v.x;
        g_rowstart[base + 1] = off; g_cursor[base + 1] = off;
        g_dis[base + 1] = rsqrtf(1.0f + (float)v.y); off += v.y;
        g_rowstart[base + 2] = off; g_cursor[base + 2] = off;
        g_dis[base + 2] = rsqrtf(1.0f + (float)v.z); off += v.z;
        g_rowstart[base + 3] = off; g_cursor[base + 3] = off;
        g_dis[base + 3] = rsqrtf(1.0f + (float)v.w);
    }
}

__global__ void fill_kernel(const void* __restrict__ ei) {
    int e = blockIdx.x * blockDim.x + threadIdx.x;
    if (e < NE) {
        int s = load_idx(ei, e);
        int d = load_idx(ei, NE + e);
        if (s >= 0 && s < NN && d >= 0 && d < NN) {
            int pos = atomicAdd(&g_cursor[d], 1);
            if (pos >= 0 && pos < NE) g_csr[pos] = s;
        }
    }
}

// ---------------- GEMM (tf32 tensor cores): [NN x K] @ [K x 128] * dis[row] -> g_G ----------
// BM=128, BN=128, BK=16, 256 threads = 8 warps in 2x4; warp tile 64x32.
// mma.sync m16n8k8 tf32, acc fp32.
__global__ __launch_bounds__(256) void gemm128_tc_kernel(
    const float* __restrict__ Aext, const float* __restrict__ W, int K, int srcH)
{
    const float* __restrict__ A = srcH ? g_H : Aext;
    __shared__ uint32_t As[16][136];   // [k][m] tf32 bits, stride 136 (8 mod 32 banks)
    __shared__ uint32_t Bs[16][136];   // [k][n] tf32 bits (only 128 cols used)

    int tid  = threadIdx.x;
    int warp = tid >> 5;
    int lane = tid & 31;
    int g    = lane >> 2;          // group id 0..7
    int t4   = lane & 3;           // thread-in-group 0..3
    int m0   = blockIdx.x * 128;
    int wm   = (warp >> 2) * 64;   // warp M offset: 0 or 64
    int wn   = (warp & 3) * 32;    // warp N offset: 0,32,64,96

    float acc[4][4][4];
#pragma unroll
    for (int mi = 0; mi < 4; mi++)
#pragma unroll
        for (int ni = 0; ni < 4; ni++)
#pragma unroll
            for (int r = 0; r < 4; r++) acc[mi][ni][r] = 0.0f;

    for (int k0 = 0; k0 < K; k0 += 16) {
        // Load A tile 128x16 (512 float4, 2 per thread), cvt to tf32, store [k][m].
#pragma unroll
        for (int i = 0; i < 2; i++) {
            int l   = tid * 2 + i;
            int row = l >> 2;
            int kc  = (l & 3) << 2;
            int gr  = m0 + row;
            float4 v = make_float4(0.f, 0.f, 0.f, 0.f);
            if (gr < NN) v = *(const float4*)(A + (size_t)gr * K + k0 + kc);
            As[kc + 0][row] = f2tf32(v.x);
            As[kc + 1][row] = f2tf32(v.y);
            As[kc + 2][row] = f2tf32(v.z);
            As[kc + 3][row] = f2tf32(v.w);
        }
        // Load B tile 16x128 (512 float4, 2 per thread), cvt to tf32.
#pragma unroll
        for (int i = 0; i < 2; i++) {
            int l  = tid * 2 + i;
            int kr = l >> 5;
            int nc = (l & 31) << 2;
            float4 v = *(const float4*)(W + (size_t)(k0 + kr) * 128 + nc);
            Bs[kr][nc + 0] = f2tf32(v.x);
            Bs[kr][nc + 1] = f2tf32(v.y);
            Bs[kr][nc + 2] = f2tf32(v.z);
            Bs[kr][nc + 3] = f2tf32(v.w);
        }
        __syncthreads();

#pragma unroll
        for (int kk = 0; kk < 16; kk += 8) {
            uint32_t af[4][4];
#pragma unroll
            for (int mi = 0; mi < 4; mi++) {
                int m = wm + mi * 16 + g;
                af[mi][0] = As[kk + t4][m];
                af[mi][1] = As[kk + t4][m + 8];
                af[mi][2] = As[kk + t4 + 4][m];
                af[mi][3] = As[kk + t4 + 4][m + 8];
            }
            uint32_t bf[4][2];
#pragma unroll
            for (int ni = 0; ni < 4; ni++) {
                int n = wn + ni * 8 + g;
                bf[ni][0] = Bs[kk + t4][n];
                bf[ni][1] = Bs[kk + t4 + 4][n];
            }
#pragma unroll
            for (int mi = 0; mi < 4; mi++)
#pragma unroll
                for (int ni = 0; ni < 4; ni++)
                    mma_tf32(acc[mi][ni], af[mi], bf[ni]);
        }
        __syncthreads();
    }

    // Epilogue: scale by dis[row], store float2s.
#pragma unroll
    for (int mi = 0; mi < 4; mi++) {
        int r0 = m0 + wm + mi * 16 + g;
        int r1 = r0 + 8;
        float d0 = (r0 < NN) ? g_dis[r0] : 0.0f;
        float d1 = (r1 < NN) ? g_dis[r1] : 0.0f;
#pragma unroll
        for (int ni = 0; ni < 4; ni++) {
            int c = wn + ni * 8 + 2 * t4;
            if (r0 < NN) {
                float2 v = make_float2(acc[mi][ni][0] * d0, acc[mi][ni][1] * d0);
                *(float2*)(g_G + (size_t)r0 * 128 + c) = v;
            }
            if (r1 < NN) {
                float2 v = make_float2(acc[mi][ni][2] * d1, acc[mi][ni][3] * d1);
                *(float2*)(g_G + (size_t)r1 * 128 + c) = v;
            }
        }
    }
}

// ---------------- GEMM: [NN x 128] @ [128 x 16], out = result * dis[row] -> g_G ----------------
// BM=512, BK=16, 256 threads; thread tile 4 rows x 8 cols. (fp32; small share of runtime)
__global__ __launch_bounds__(256) void gemm16_kernel(const float* __restrict__ W3)
{
    __shared__ float As[16][520];
    __shared__ float Bs[16][16];

    int tid = threadIdx.x;
    int m0  = blockIdx.x * 512;
    int tx  = tid & 1;
    int ty  = tid >> 1;

    float acc[4][8];
#pragma unroll
    for (int r = 0; r < 4; r++)
#pragma unroll
        for (int c = 0; c < 8; c++) acc[r][c] = 0.0f;

    for (int k0 = 0; k0 < 128; k0 += 16) {
#pragma unroll
        for (int i = 0; i < 8; i++) {
            int l   = i * 256 + tid;
            int row = l >> 2;
            int kc  = (l & 3) << 2;
            int gr  = m0 + row;
            float4 v = make_float4(0.f, 0.f, 0.f, 0.f);
            if (gr < NN) v = *(const float4*)(g_H + (size_t)gr * 128 + k0 + kc);
            As[kc + 0][row] = v.x;
            As[kc + 1][row] = v.y;
            As[kc + 2][row] = v.z;
            As[kc + 3][row] = v.w;
        }
        if (tid < 64) {
            int kr = tid >> 2;
            int nc = (tid & 3) << 2;
            *(float4*)&Bs[kr][nc] = *(const float4*)(W3 + (size_t)(k0 + kr) * 16 + nc);
        }
        __syncthreads();

#pragma unroll
        for (int k = 0; k < 16; k++) {
            float4 av = *(const float4*)&As[k][ty * 4];
            float a[4] = {av.x, av.y, av.z, av.w};
            float4 b0 = *(const float4*)&Bs[k][tx * 8];
            float4 b1 = *(const float4*)&Bs[k][tx * 8 + 4];
            float bb[8] = {b0.x,b0.y,b0.z,b0.w,b1.x,b1.y,b1.z,b1.w};
#pragma unroll
            for (int r = 0; r < 4; r++)
#pragma unroll
                for (int c = 0; c < 8; c++)
                    acc[r][c] += a[r] * bb[c];
        }
        __syncthreads();
    }

#pragma unroll
    for (int r = 0; r < 4; r++) {
        int gr = m0 + ty * 4 + r;
        if (gr < NN) {
            float d = g_dis[gr];
            float4 v0 = make_float4(acc[r][0]*d, acc[r][1]*d, acc[r][2]*d, acc[r][3]*d);
            float4 v1 = make_float4(acc[r][4]*d, acc[r][5]*d, acc[r][6]*d, acc[r][7]*d);
            *(float4*)(g_G + (size_t)gr * 16 + tx * 8)     = v0;
            *(float4*)(g_G + (size_t)gr * 16 + tx * 8 + 4) = v1;
        }
    }
}

// ---------------- Aggregation (128-wide): H = relu(dis[i]*(G[i] + sum G[src]) + b) ----------------
__global__ __launch_bounds__(256) void agg128_kernel(const float* __restrict__ bias)
{
    int gt   = blockIdx.x * blockDim.x + threadIdx.x;
    int node = gt >> 5;
    int lane = gt & 31;
    if (node >= NN) return;

    const float4* __restrict__ Gv = (const float4*)g_G;
    float4 acc = Gv[(size_t)node * 32 + lane];

    int s0 = g_rowstart[node];
    int s1 = g_rowstart[node + 1];
    for (int j = s0; j < s1; j++) {
        int s = g_csr[j];
        acc = f4add(acc, Gv[(size_t)s * 32 + lane]);
    }

    float d = g_dis[node];
    float4 b = ((const float4*)bias)[lane];
    float4 r;
    r.x = fmaxf(acc.x * d + b.x, 0.0f);
    r.y = fmaxf(acc.y * d + b.y, 0.0f);
    r.z = fmaxf(acc.z * d + b.z, 0.0f);
    r.w = fmaxf(acc.w * d + b.w, 0.0f);
    ((float4*)g_H)[(size_t)node * 32 + lane] = r;
}

// ---------------- Aggregation (16-wide, final) ----------------
__global__ __launch_bounds__(256) void agg16_kernel(const float* __restrict__ bias,
                                                    float* __restrict__ out)
{
    int gt   = blockIdx.x * blockDim.x + threadIdx.x;
    int node = gt >> 2;
    int q    = gt & 3;
    if (node >= NN) return;

    const float4* __restrict__ Gv = (const float4*)g_G;
    float4 acc = Gv[(size_t)node * 4 + q];

    int s0 = g_rowstart[node];
    int s1 = g_rowstart[node + 1];
    for (int j = s0; j < s1; j++) {
        int s = g_csr[j];
        acc = f4add(acc, Gv[(size_t)s * 4 + q]);
    }

    float d = g_dis[node];
    float4 b = ((const float4*)bias)[q];
    float4 r;
    r.x = acc.x * d + b.x;
    r.y = acc.y * d + b.y;
    r.z = acc.z * d + b.z;
    r.w = acc.w * d + b.w;
    ((float4*)out)[(size_t)node * 4 + q] = r;
}

// ---------------- launch ----------------
extern "C" void kernel_launch(void* const* d_in, const int* in_sizes, int n_in,
                              void* d_out, int out_size)
{
    const float* x  = (const float*)d_in[0];
    const void*  ei = d_in[1];                 // int32 or int64, detected on device
    const float* W1 = (const float*)d_in[2];
    const float* b1 = (const float*)d_in[3];
    const float* W2 = (const float*)d_in[4];
    const float* b2 = (const float*)d_in[5];
    const float* W3 = (const float*)d_in[6];
    const float* b3 = (const float*)d_in[7];
    float* out = (float*)d_out;

    // preprocessing: dtype detect -> degrees -> hierarchical scan -> CSR
    detect_kernel<<<1, 32>>>(ei);
    zero_deg_kernel<<<(NN + 255) / 256, 256>>>();
    deg_kernel<<<(NE + 255) / 256, 256>>>(ei);
    scan1_kernel<<<SCAN_BLOCKS, 256>>>();
    scan2_kernel<<<1, 64>>>();
    scan3_kernel<<<SCAN_BLOCKS, 256>>>();
    fill_kernel<<<(NE + 255) / 256, 256>>>(ei);

    const int gemm_blocks   = (NN + 127) / 128;        // 391
    const int agg128_blocks = (NN * 32 + 255) / 256;   // 6250
    const int agg16_blocks  = (NN * 4 + 255) / 256;    // 782
    const int gemm16_blocks = (NN + 511) / 512;        // 98

    // Layer 1: K=256 (tf32 tensor cores)
    gemm128_tc_kernel<<<gemm_blocks, 256>>>(x, W1, 256, 0);
    agg128_kernel<<<agg128_blocks, 256>>>(b1);

    // Layer 2: K=128 (tf32 tensor cores)
    gemm128_tc_kernel<<<gemm_blocks, 256>>>(nullptr, W2, 128, 1);
    agg128_kernel<<<agg128_blocks, 256>>>(b2);

    // Layer 3: 128 -> 16, no relu (fp32)
    gemm16_kernel<<<gemm16_blocks, 256>>>(W3);
    agg16_kernel<<<agg16_blocks, 256>>>(b3, out);
}

// round 7
// speedup vs baseline: 2.2643x; 1.0668x over previous
#include <cuda_runtime.h>
#include <cuda_bf16.h>
#include <cuda_fp16.h>
#include <cstdint>

// GCN_26817775797032: 3-layer GCN, N=50000 nodes, E=640000 edges,
// dims 256 -> 128 -> 128 -> 16.
//
// R7: G gather table stored in fp16 (same 10-bit mantissa as the tf32 path
// already in use) -> agg128 L2 traffic halved (512B -> 256B per edge).
// detect folded into zero_deg (one fewer launch).

#define NN 50000
#define NE 640000
#define HID 128
#define NCLS 16
#define NT4 12500           // NN/4, exact
#define SCAN_BLOCKS 49      // ceil(12500/256)

// ---------------- device scratch (no allocs allowed) ----------------
__device__ int   g_is64;
__device__ __align__(16) int g_deg[NN];
__device__ int   g_rowstart[NN + 1];
__device__ int   g_cursor[NN];
__device__ int   g_csr[NE];
__device__ float g_dis[NN];
__device__ int   g_blocksum[SCAN_BLOCKS];
__device__ int   g_blockoff[SCAN_BLOCKS];
__device__ __align__(16) __half g_Gh[(size_t)NN * HID];  // fp16 gather table (layers 1,2)
__device__ __align__(16) float  g_G16[(size_t)NN * NCLS]; // fp32 gather table (layer 3)
__device__ __align__(16) float  g_H[(size_t)NN * HID];    // layer activations (fp32)

// ---------------- helpers ----------------
__device__ __forceinline__ float4 f4add(float4 a, float4 b) {
    a.x += b.x; a.y += b.y; a.z += b.z; a.w += b.w; return a;
}

__device__ __forceinline__ uint32_t f2tf32(float f) {
    uint32_t u;
    asm("cvt.rna.tf32.f32 %0, %1;" : "=r"(u) : "f"(f));
    return u;
}

__device__ __forceinline__ void mma_tf32(float* d, const uint32_t* a, const uint32_t* b) {
    asm volatile(
        "mma.sync.aligned.m16n8k8.row.col.f32.tf32.tf32.f32 "
        "{%0,%1,%2,%3}, {%4,%5,%6,%7}, {%8,%9}, {%0,%1,%2,%3};"
        : "+f"(d[0]), "+f"(d[1]), "+f"(d[2]), "+f"(d[3])
        : "r"(a[0]), "r"(a[1]), "r"(a[2]), "r"(a[3]), "r"(b[0]), "r"(b[1]));
}

// Load edge-index element i (element index in [0, 2*NE)), dtype-dispatched.
__device__ __forceinline__ int load_idx(const void* __restrict__ ei, int i) {
    if (g_is64) return (int)((const long long*)ei)[i];
    return ((const int*)ei)[i];
}

// ---------------- preprocessing ----------------
// zero degrees + dtype detection (warp 0 of block 0).
__global__ void zero_deg_kernel(const void* __restrict__ ei) {
    int i = blockIdx.x * blockDim.x + threadIdx.x;
    if (i < NN) g_deg[i] = 0;
    if (blockIdx.x == 0 && threadIdx.x < 32) {
        const long long* p = (const long long*)ei;
        long long v = p[threadIdx.x];
        unsigned bad = __ballot_sync(0xFFFFFFFFu, v < 0 || v >= NN);
        if (threadIdx.x == 0) g_is64 = (bad == 0u);
    }
}

__global__ void deg_kernel(const void* __restrict__ ei) {
    int e = blockIdx.x * blockDim.x + threadIdx.x;
    if (e < NE) {
        int d = load_idx(ei, NE + e);
        if (d >= 0 && d < NN) atomicAdd(&g_deg[d], 1);
    }
}

// ---- hierarchical scan: 49 blocks x 256 threads, 4 nodes/thread ----
__global__ __launch_bounds__(256) void scan1_kernel() {
    int t = blockIdx.x * 256 + threadIdx.x;
    int s = 0;
    if (t < NT4) {
        int4 v = ((const int4*)g_deg)[t];
        s = v.x + v.y + v.z + v.w;
    }
    __shared__ int ws[8];
#pragma unroll
    for (int o = 16; o > 0; o >>= 1) s += __shfl_down_sync(0xFFFFFFFFu, s, o);
    if ((threadIdx.x & 31) == 0) ws[threadIdx.x >> 5] = s;
    __syncthreads();
    if (threadIdx.x < 8) {
        int v = ws[threadIdx.x];
#pragma unroll
        for (int o = 4; o > 0; o >>= 1) v += __shfl_down_sync(0xFFu, v, o);
        if (threadIdx.x == 0) g_blocksum[blockIdx.x] = v;
    }
}

__global__ void scan2_kernel() {
    __shared__ int sh[64];
    int t = threadIdx.x;
    sh[t] = (t < SCAN_BLOCKS) ? g_blocksum[t] : 0;
    __syncthreads();
#pragma unroll
    for (int d = 1; d < 64; d <<= 1) {
        int v = (t >= d) ? sh[t - d] : 0;
        __syncthreads();
        sh[t] += v;
        __syncthreads();
    }
    if (t < SCAN_BLOCKS) g_blockoff[t] = (t == 0) ? 0 : sh[t - 1];
    if (t == SCAN_BLOCKS - 1) g_rowstart[NN] = sh[SCAN_BLOCKS - 1];
}

__global__ __launch_bounds__(256) void scan3_kernel() {
    int tid  = threadIdx.x;
    int lane = tid & 31;
    int warp = tid >> 5;
    int t    = blockIdx.x * 256 + tid;

    int4 v = make_int4(0, 0, 0, 0);
    if (t < NT4) v = ((const int4*)g_deg)[t];
    int s = v.x + v.y + v.z + v.w;

    int inc = s;
#pragma unroll
    for (int o = 1; o < 32; o <<= 1) {
        int u = __shfl_up_sync(0xFFFFFFFFu, inc, o);
        if (lane >= o) inc += u;
    }
    __shared__ int wsum[8], woff[8];
    if (lane == 31) wsum[warp] = inc;
    __syncthreads();
    if (tid < 8) {
        int w  = wsum[tid];
        int wi = w;
#pragma unroll
        for (int o = 1; o < 8; o <<= 1) {
            int u = __shfl_up_sync(0xFFu, wi, o);
            if (tid >= o) wi += u;
        }
        woff[tid] = wi - w;
    }
    __syncthreads();

    if (t < NT4) {
        int off = (inc - s) + woff[warp] + g_blockoff[blockIdx.x];
        int base = t * 4;
        g_rowstart[base + 0] = off; g_cursor[base + 0] = off;
        g_dis[base + 0] = rsqrtf(1.0f + (float)v.x); off += v.x;
        g_rowstart[base + 1] = off; g_cursor[base + 1] = off;
        g_dis[base + 1] = rsqrtf(1.0f + (float)v.y); off += v.y;
        g_rowstart[base + 2] = off; g_cursor[base + 2] = off;
        g_dis[base + 2] = rsqrtf(1.0f + (float)v.z); off += v.z;
        g_rowstart[base + 3] = off; g_cursor[base + 3] = off;
        g_dis[base + 3] = rsqrtf(1.0f + (float)v.w);
    }
}

__global__ void fill_kernel(const void* __restrict__ ei) {
    int e = blockIdx.x * blockDim.x + threadIdx.x;
    if (e < NE) {
        int s = load_idx(ei, e);
        int d = load_idx(ei, NE + e);
        if (s >= 0 && s < NN && d >= 0 && d < NN) {
            int pos = atomicAdd(&g_cursor[d], 1);
            if (pos >= 0 && pos < NE) g_csr[pos] = s;
        }
    }
}

// ---------------- GEMM (tf32 tensor cores): [NN x K] @ [K x 128] * dis[row] -> g_Gh (fp16) ----
// BM=128, BN=128, BK=16, 256 threads = 8 warps in 2x4; warp tile 64x32.
__global__ __launch_bounds__(256) void gemm128_tc_kernel(
    const float* __restrict__ Aext, const float* __restrict__ W, int K, int srcH)
{
    const float* __restrict__ A = srcH ? g_H : Aext;
    __shared__ uint32_t As[16][136];   // [k][m] tf32 bits, stride 136 (8 mod 32 banks)
    __shared__ uint32_t Bs[16][136];   // [k][n] tf32 bits (only 128 cols used)

    int tid  = threadIdx.x;
    int warp = tid >> 5;
    int lane = tid & 31;
    int g    = lane >> 2;          // group id 0..7
    int t4   = lane & 3;           // thread-in-group 0..3
    int m0   = blockIdx.x * 128;
    int wm   = (warp >> 2) * 64;   // warp M offset: 0 or 64
    int wn   = (warp & 3) * 32;    // warp N offset: 0,32,64,96

    float acc[4][4][4];
#pragma unroll
    for (int mi = 0; mi < 4; mi++)
#pragma unroll
        for (int ni = 0; ni < 4; ni++)
#pragma unroll
            for (int r = 0; r < 4; r++) acc[mi][ni][r] = 0.0f;

    for (int k0 = 0; k0 < K; k0 += 16) {
        // Load A tile 128x16 (512 float4, 2 per thread), cvt to tf32, store [k][m].
#pragma unroll
        for (int i = 0; i < 2; i++) {
            int l   = tid * 2 + i;
            int row = l >> 2;
            int kc  = (l & 3) << 2;
            int gr  = m0 + row;
            float4 v = make_float4(0.f, 0.f, 0.f, 0.f);
            if (gr < NN) v = *(const float4*)(A + (size_t)gr * K + k0 + kc);
            As[kc + 0][row] = f2tf32(v.x);
            As[kc + 1][row] = f2tf32(v.y);
            As[kc + 2][row] = f2tf32(v.z);
            As[kc + 3][row] = f2tf32(v.w);
        }
        // Load B tile 16x128 (512 float4, 2 per thread), cvt to tf32.
#pragma unroll
        for (int i = 0; i < 2; i++) {
            int l  = tid * 2 + i;
            int kr = l >> 5;
            int nc = (l & 31) << 2;
            float4 v = *(const float4*)(W + (size_t)(k0 + kr) * 128 + nc);
            Bs[kr][nc + 0] = f2tf32(v.x);
            Bs[kr][nc + 1] = f2tf32(v.y);
            Bs[kr][nc + 2] = f2tf32(v.z);
            Bs[kr][nc + 3] = f2tf32(v.w);
        }
        __syncthreads();

#pragma unroll
        for (int kk = 0; kk < 16; kk += 8) {
            uint32_t af[4][4];
#pragma unroll
            for (int mi = 0; mi < 4; mi++) {
                int m = wm + mi * 16 + g;
                af[mi][0] = As[kk + t4][m];
                af[mi][1] = As[kk + t4][m + 8];
                af[mi][2] = As[kk + t4 + 4][m];
                af[mi][3] = As[kk + t4 + 4][m + 8];
            }
            uint32_t bf[4][2];
#pragma unroll
            for (int ni = 0; ni < 4; ni++) {
                int n = wn + ni * 8 + g;
                bf[ni][0] = Bs[kk + t4][n];
                bf[ni][1] = Bs[kk + t4 + 4][n];
            }
#pragma unroll
            for (int mi = 0; mi < 4; mi++)
#pragma unroll
                for (int ni = 0; ni < 4; ni++)
                    mma_tf32(acc[mi][ni], af[mi], bf[ni]);
        }
        __syncthreads();
    }

    // Epilogue: scale by dis[row], pack to half2, store to g_Gh.
#pragma unroll
    for (int mi = 0; mi < 4; mi++) {
        int r0 = m0 + wm + mi * 16 + g;
        int r1 = r0 + 8;
        float d0 = (r0 < NN) ? g_dis[r0] : 0.0f;
        float d1 = (r1 < NN) ? g_dis[r1] : 0.0f;
#pragma unroll
        for (int ni = 0; ni < 4; ni++) {
            int c = wn + ni * 8 + 2 * t4;
            if (r0 < NN) {
                __half2 h = __floats2half2_rn(acc[mi][ni][0] * d0, acc[mi][ni][1] * d0);
                *(__half2*)(g_Gh + (size_t)r0 * 128 + c) = h;
            }
            if (r1 < NN) {
                __half2 h = __floats2half2_rn(acc[mi][ni][2] * d1, acc[mi][ni][3] * d1);
                *(__half2*)(g_Gh + (size_t)r1 * 128 + c) = h;
            }
        }
    }
}

// ---------------- GEMM: [NN x 128] @ [128 x 16], out = result * dis[row] -> g_G16 (fp32) ------
// BM=512, BK=16, 256 threads; thread tile 4 rows x 8 cols.
__global__ __launch_bounds__(256) void gemm16_kernel(const float* __restrict__ W3)
{
    __shared__ float As[16][520];
    __shared__ float Bs[16][16];

    int tid = threadIdx.x;
    int m0  = blockIdx.x * 512;
    int tx  = tid & 1;
    int ty  = tid >> 1;

    float acc[4][8];
#pragma unroll
    for (int r = 0; r < 4; r++)
#pragma unroll
        for (int c = 0; c < 8; c++) acc[r][c] = 0.0f;

    for (int k0 = 0; k0 < 128; k0 += 16) {
#pragma unroll
        for (int i = 0; i < 8; i++) {
            int l   = i * 256 + tid;
            int row = l >> 2;
            int kc  = (l & 3) << 2;
            int gr  = m0 + row;
            float4 v = make_float4(0.f, 0.f, 0.f, 0.f);
            if (gr < NN) v = *(const float4*)(g_H + (size_t)gr * 128 + k0 + kc);
            As[kc + 0][row] = v.x;
            As[kc + 1][row] = v.y;
            As[kc + 2][row] = v.z;
            As[kc + 3][row] = v.w;
        }
        if (tid < 64) {
            int kr = tid >> 2;
            int nc = (tid & 3) << 2;
            *(float4*)&Bs[kr][nc] = *(const float4*)(W3 + (size_t)(k0 + kr) * 16 + nc);
        }
        __syncthreads();

#pragma unroll
        for (int k = 0; k < 16; k++) {
            float4 av = *(const float4*)&As[k][ty * 4];
            float a[4] = {av.x, av.y, av.z, av.w};
            float4 b0 = *(const float4*)&Bs[k][tx * 8];
            float4 b1 = *(const float4*)&Bs[k][tx * 8 + 4];
            float bb[8] = {b0.x,b0.y,b0.z,b0.w,b1.x,b1.y,b1.z,b1.w};
#pragma unroll
            for (int r = 0; r < 4; r++)
#pragma unroll
                for (int c = 0; c < 8; c++)
                    acc[r][c] += a[r] * bb[c];
        }
        __syncthreads();
    }

#pragma unroll
    for (int r = 0; r < 4; r++) {
        int gr = m0 + ty * 4 + r;
        if (gr < NN) {
            float d = g_dis[gr];
            float4 v0 = make_float4(acc[r][0]*d, acc[r][1]*d, acc[r][2]*d, acc[r][3]*d);
            float4 v1 = make_float4(acc[r][4]*d, acc[r][5]*d, acc[r][6]*d, acc[r][7]*d);
            *(float4*)(g_G16 + (size_t)gr * 16 + tx * 8)     = v0;
            *(float4*)(g_G16 + (size_t)gr * 16 + tx * 8 + 4) = v1;
        }
    }
}

// ---------------- Aggregation (128-wide, fp16 gather): ----------------
// H = relu(dis[i]*(G[i] + sum G[src]) + b), accumulate fp32.
// One warp per node; lane l handles halfs [4l, 4l+4) = one uint2 (8B).
__global__ __launch_bounds__(256) void agg128_kernel(const float* __restrict__ bias)
{
    int gt   = blockIdx.x * blockDim.x + threadIdx.x;
    int node = gt >> 5;
    int lane = gt & 31;
    if (node >= NN) return;

    const uint2* __restrict__ Gv = (const uint2*)g_Gh;   // row = 32 uint2

    uint2 u = Gv[(size_t)node * 32 + lane];              // self-loop term
    float2 p0 = __half22float2(*(__half2*)&u.x);
    float2 p1 = __half22float2(*(__half2*)&u.y);
    float4 acc = make_float4(p0.x, p0.y, p1.x, p1.y);

    int s0 = g_rowstart[node];
    int s1 = g_rowstart[node + 1];
    for (int j = s0; j < s1; j++) {
        int s = g_csr[j];
        uint2 v = Gv[(size_t)s * 32 + lane];
        float2 q0 = __half22float2(*(__half2*)&v.x);
        float2 q1 = __half22float2(*(__half2*)&v.y);
        acc.x += q0.x; acc.y += q0.y; acc.z += q1.x; acc.w += q1.y;
    }

    float d = g_dis[node];
    float4 b = ((const float4*)bias)[lane];
    float4 r;
    r.x = fmaxf(acc.x * d + b.x, 0.0f);
    r.y = fmaxf(acc.y * d + b.y, 0.0f);
    r.z = fmaxf(acc.z * d + b.z, 0.0f);
    r.w = fmaxf(acc.w * d + b.w, 0.0f);
    ((float4*)g_H)[(size_t)node * 32 + lane] = r;
}

// ---------------- Aggregation (16-wide, final, fp32) ----------------
__global__ __launch_bounds__(256) void agg16_kernel(const float* __restrict__ bias,
                                                    float* __restrict__ out)
{
    int gt   = blockIdx.x * blockDim.x + threadIdx.x;
    int node = gt >> 2;
    int q    = gt & 3;
    if (node >= NN) return;

    const float4* __restrict__ Gv = (const float4*)g_G16;
    float4 acc = Gv[(size_t)node * 4 + q];

    int s0 = g_rowstart[node];
    int s1 = g_rowstart[node + 1];
    for (int j = s0; j < s1; j++) {
        int s = g_csr[j];
        acc = f4add(acc, Gv[(size_t)s * 4 + q]);
    }

    float d = g_dis[node];
    float4 b = ((const float4*)bias)[q];
    float4 r;
    r.x = acc.x * d + b.x;
    r.y = acc.y * d + b.y;
    r.z = acc.z * d + b.z;
    r.w = acc.w * d + b.w;
    ((float4*)out)[(size_t)node * 4 + q] = r;
}

// ---------------- launch ----------------
extern "C" void kernel_launch(void* const* d_in, const int* in_sizes, int n_in,
                              void* d_out, int out_size)
{
    const float* x  = (const float*)d_in[0];
    const void*  ei = d_in[1];                 // int32 or int64, detected on device
    const float* W1 = (const float*)d_in[2];
    const float* b1 = (const float*)d_in[3];
    const float* W2 = (const float*)d_in[4];
    const float* b2 = (const float*)d_in[5];
    const float* W3 = (const float*)d_in[6];
    const float* b3 = (const float*)d_in[7];
    float* out = (float*)d_out;

    // preprocessing: zero+detect -> degrees -> hierarchical scan -> CSR
    zero_deg_kernel<<<(NN + 255) / 256, 256>>>(ei);
    deg_kernel<<<(NE + 255) / 256, 256>>>(ei);
    scan1_kernel<<<SCAN_BLOCKS, 256>>>();
    scan2_kernel<<<1, 64>>>();
    scan3_kernel<<<SCAN_BLOCKS, 256>>>();
    fill_kernel<<<(NE + 255) / 256, 256>>>(ei);

    const int gemm_blocks   = (NN + 127) / 128;        // 391
    const int agg128_blocks = (NN * 32 + 255) / 256;   // 6250
    const int agg16_blocks  = (NN * 4 + 255) / 256;    // 782
    const int gemm16_blocks = (NN + 511) / 512;        // 98

    // Layer 1: K=256 (tf32 tensor cores, fp16 G)
    gemm128_tc_kernel<<<gemm_blocks, 256>>>(x, W1, 256, 0);
    agg128_kernel<<<agg128_blocks, 256>>>(b1);

    // Layer 2: K=128 (tf32 tensor cores, fp16 G)
    gemm128_tc_kernel<<<gemm_blocks, 256>>>(nullptr, W2, 128, 1);
    agg128_kernel<<<agg128_blocks, 256>>>(b2);

    // Layer 3: 128 -> 16, no relu (fp32)
    gemm16_kernel<<<gemm16_blocks, 256>>>(W3);
    agg16_kernel<<<agg16_blocks, 256>>>(b3, out);
}

// round 8
// speedup vs baseline: 2.4520x; 1.0829x over previous
#include <cuda_runtime.h>
#include <cuda_bf16.h>
#include <cuda_fp16.h>
#include <cstdint>

// GCN_26817775797032: 3-layer GCN, N=50000 nodes, E=640000 edges,
// dims 256 -> 128 -> 128 -> 16.
//
// R8: (a) GEMM-L1 decoupled from preprocessing (dis folded into agg) and run
// on a forked capture branch, overlapping zero/deg/scan/fill; (b) 3-kernel
// scan fused into one decoupled-lookback kernel; (c) agg edge loop 4x
// unrolled for MLP.

#define NN 50000
#define NE 640000
#define HID 128
#define NCLS 16
#define NT4 12500           // NN/4, exact
#define SCAN_BLOCKS 49      // ceil(12500/256)

// ---------------- device scratch (no allocs allowed) ----------------
__device__ int   g_is64;
__device__ __align__(16) int g_deg[NN];
__device__ int   g_rowstart[NN + 1];
__device__ int   g_cursor[NN];
__device__ int   g_csr[NE];
__device__ float g_dis[NN];
__device__ unsigned long long g_scanstate[SCAN_BLOCKS];
__device__ __align__(16) __half g_Gh[(size_t)NN * HID];   // fp16 gather table (layers 1,2)
__device__ __align__(16) float  g_G16[(size_t)NN * NCLS]; // fp32 gather table (layer 3)
__device__ __align__(16) float  g_H[(size_t)NN * HID];    // layer activations (fp32)

// ---------------- helpers ----------------
__device__ __forceinline__ float4 f4add(float4 a, float4 b) {
    a.x += b.x; a.y += b.y; a.z += b.z; a.w += b.w; return a;
}

__device__ __forceinline__ uint32_t f2tf32(float f) {
    uint32_t u;
    asm("cvt.rna.tf32.f32 %0, %1;" : "=r"(u) : "f"(f));
    return u;
}

__device__ __forceinline__ void mma_tf32(float* d, const uint32_t* a, const uint32_t* b) {
    asm volatile(
        "mma.sync.aligned.m16n8k8.row.col.f32.tf32.tf32.f32 "
        "{%0,%1,%2,%3}, {%4,%5,%6,%7}, {%8,%9}, {%0,%1,%2,%3};"
        : "+f"(d[0]), "+f"(d[1]), "+f"(d[2]), "+f"(d[3])
        : "r"(a[0]), "r"(a[1]), "r"(a[2]), "r"(a[3]), "r"(b[0]), "r"(b[1]));
}

__device__ __forceinline__ int load_idx(const void* __restrict__ ei, int i) {
    if (g_is64) return (int)((const long long*)ei)[i];
    return ((const int*)ei)[i];
}

__device__ __forceinline__ float4 h8_to_f4_sum(uint2 v, float w, float4 acc) {
    float2 q0 = __half22float2(*(__half2*)&v.x);
    float2 q1 = __half22float2(*(__half2*)&v.y);
    acc.x += w * q0.x; acc.y += w * q0.y;
    acc.z += w * q1.x; acc.w += w * q1.y;
    return acc;
}

// ---------------- preprocessing ----------------
// zero degrees + scan states + dtype detection (warp 0 of block 0).
__global__ void zero_deg_kernel(const void* __restrict__ ei) {
    int i = blockIdx.x * blockDim.x + threadIdx.x;
    if (i < NN) g_deg[i] = 0;
    if (i < SCAN_BLOCKS) g_scanstate[i] = 0ULL;
    if (blockIdx.x == 0 && threadIdx.x < 32) {
        const long long* p = (const long long*)ei;
        long long v = p[threadIdx.x];
        unsigned bad = __ballot_sync(0xFFFFFFFFu, v < 0 || v >= NN);
        if (threadIdx.x == 0) g_is64 = (bad == 0u);
    }
}

__global__ void deg_kernel(const void* __restrict__ ei) {
    int e = blockIdx.x * blockDim.x + threadIdx.x;
    if (e < NE) {
        int d = load_idx(ei, NE + e);
        if (d >= 0 && d < NN) atomicAdd(&g_deg[d], 1);
    }
}

// ---- fused single-pass scan (decoupled lookback), 49 blocks x 256 threads x 4 nodes ----
__global__ __launch_bounds__(256) void scan_fused_kernel() {
    int tid  = threadIdx.x;
    int lane = tid & 31;
    int warp = tid >> 5;
    int bid  = blockIdx.x;
    int t    = bid * 256 + tid;

    int4 v = make_int4(0, 0, 0, 0);
    if (t < NT4) v = ((const int4*)g_deg)[t];
    int s = v.x + v.y + v.z + v.w;

    // warp inclusive scan
    int inc = s;
#pragma unroll
    for (int o = 1; o < 32; o <<= 1) {
        int u = __shfl_up_sync(0xFFFFFFFFu, inc, o);
        if (lane >= o) inc += u;
    }
    __shared__ int wsum[8], woff[8];
    __shared__ int blk_excl;
    if (lane == 31) wsum[warp] = inc;
    __syncthreads();
    if (tid < 8) {
        int w  = wsum[tid];
        int wi = w;
#pragma unroll
        for (int o = 1; o < 8; o <<= 1) {
            int u = __shfl_up_sync(0xFFu, wi, o);
            if (tid >= o) wi += u;
        }
        woff[tid] = wi - w;   // exclusive warp offset
    }
    __syncthreads();

    if (tid == 0) {
        long long block_total = (long long)(woff[7] + wsum[7]);
        long long excl = 0;
        if (bid == 0) {
            atomicExch(&g_scanstate[0],
                       (((unsigned long long)block_total) << 2) | 2ULL);
        } else {
            atomicExch(&g_scanstate[bid],
                       (((unsigned long long)block_total) << 2) | 1ULL);
            int p = bid - 1;
            while (true) {
                unsigned long long st = atomicAdd(&g_scanstate[p], 0ULL);
                unsigned f = (unsigned)(st & 3ULL);
                if (f == 2u) { excl += (long long)(st >> 2); break; }
                if (f == 1u) { excl += (long long)(st >> 2); p--; }
            }
            atomicExch(&g_scanstate[bid],
                       (((unsigned long long)(excl + block_total)) << 2) | 2ULL);
        }
        blk_excl = (int)excl;
        if (bid == SCAN_BLOCKS - 1) g_rowstart[NN] = (int)(excl + block_total);
    }
    __syncthreads();

    if (t < NT4) {
        int off = (inc - s) + woff[warp] + blk_excl;
        int base = t * 4;
        g_rowstart[base + 0] = off; g_cursor[base + 0] = off;
        g_dis[base + 0] = rsqrtf(1.0f + (float)v.x); off += v.x;
        g_rowstart[base + 1] = off; g_cursor[base + 1] = off;
        g_dis[base + 1] = rsqrtf(1.0f + (float)v.y); off += v.y;
        g_rowstart[base + 2] = off; g_cursor[base + 2] = off;
        g_dis[base + 2] = rsqrtf(1.0f + (float)v.z); off += v.z;
        g_rowstart[base + 3] = off; g_cursor[base + 3] = off;
        g_dis[base + 3] = rsqrtf(1.0f + (float)v.w);
    }
}

__global__ void fill_kernel(const void* __restrict__ ei) {
    int e = blockIdx.x * blockDim.x + threadIdx.x;
    if (e < NE) {
        int s = load_idx(ei, e);
        int d = load_idx(ei, NE + e);
        if (s >= 0 && s < NN && d >= 0 && d < NN) {
            int pos = atomicAdd(&g_cursor[d], 1);
            if (pos >= 0 && pos < NE) g_csr[pos] = s;
        }
    }
}

// ---------------- GEMM (tf32 tensor cores): [NN x K] @ [K x 128] -> g_Gh (fp16) ----
// scale_dis: multiply rows by dis[row] in epilogue (layer 2); layer 1 runs
// before dis exists and defers the norm to the aggregation.
__global__ __launch_bounds__(256) void gemm128_tc_kernel(
    const float* __restrict__ Aext, const float* __restrict__ W, int K, int srcH,
    int scale_dis)
{
    const float* __restrict__ A = srcH ? g_H : Aext;
    __shared__ uint32_t As[16][136];
    __shared__ uint32_t Bs[16][136];

    int tid  = threadIdx.x;
    int warp = tid >> 5;
    int lane = tid & 31;
    int g    = lane >> 2;
    int t4   = lane & 3;
    int m0   = blockIdx.x * 128;
    int wm   = (warp >> 2) * 64;
    int wn   = (warp & 3) * 32;

    float acc[4][4][4];
#pragma unroll
    for (int mi = 0; mi < 4; mi++)
#pragma unroll
        for (int ni = 0; ni < 4; ni++)
#pragma unroll
            for (int r = 0; r < 4; r++) acc[mi][ni][r] = 0.0f;

    for (int k0 = 0; k0 < K; k0 += 16) {
#pragma unroll
        for (int i = 0; i < 2; i++) {
            int l   = tid * 2 + i;
            int row = l >> 2;
            int kc  = (l & 3) << 2;
            int gr  = m0 + row;
            float4 v = make_float4(0.f, 0.f, 0.f, 0.f);
            if (gr < NN) v = *(const float4*)(A + (size_t)gr * K + k0 + kc);
            As[kc + 0][row] = f2tf32(v.x);
            As[kc + 1][row] = f2tf32(v.y);
            As[kc + 2][row] = f2tf32(v.z);
            As[kc + 3][row] = f2tf32(v.w);
        }
#pragma unroll
        for (int i = 0; i < 2; i++) {
            int l  = tid * 2 + i;
            int kr = l >> 5;
            int nc = (l & 31) << 2;
            float4 v = *(const float4*)(W + (size_t)(k0 + kr) * 128 + nc);
            Bs[kr][nc + 0] = f2tf32(v.x);
            Bs[kr][nc + 1] = f2tf32(v.y);
            Bs[kr][nc + 2] = f2tf32(v.z);
            Bs[kr][nc + 3] = f2tf32(v.w);
        }
        __syncthreads();

#pragma unroll
        for (int kk = 0; kk < 16; kk += 8) {
            uint32_t af[4][4];
#pragma unroll
            for (int mi = 0; mi < 4; mi++) {
                int m = wm + mi * 16 + g;
                af[mi][0] = As[kk + t4][m];
                af[mi][1] = As[kk + t4][m + 8];
                af[mi][2] = As[kk + t4 + 4][m];
                af[mi][3] = As[kk + t4 + 4][m + 8];
            }
            uint32_t bf[4][2];
#pragma unroll
            for (int ni = 0; ni < 4; ni++) {
                int n = wn + ni * 8 + g;
                bf[ni][0] = Bs[kk + t4][n];
                bf[ni][1] = Bs[kk + t4 + 4][n];
            }
#pragma unroll
            for (int mi = 0; mi < 4; mi++)
#pragma unroll
                for (int ni = 0; ni < 4; ni++)
                    mma_tf32(acc[mi][ni], af[mi], bf[ni]);
        }
        __syncthreads();
    }

#pragma unroll
    for (int mi = 0; mi < 4; mi++) {
        int r0 = m0 + wm + mi * 16 + g;
        int r1 = r0 + 8;
        float d0 = 1.0f, d1 = 1.0f;
        if (scale_dis) {
            d0 = (r0 < NN) ? g_dis[r0] : 0.0f;
            d1 = (r1 < NN) ? g_dis[r1] : 0.0f;
        }
#pragma unroll
        for (int ni = 0; ni < 4; ni++) {
            int c = wn + ni * 8 + 2 * t4;
            if (r0 < NN) {
                __half2 h = __floats2half2_rn(acc[mi][ni][0] * d0, acc[mi][ni][1] * d0);
                *(__half2*)(g_Gh + (size_t)r0 * 128 + c) = h;
            }
            if (r1 < NN) {
                __half2 h = __floats2half2_rn(acc[mi][ni][2] * d1, acc[mi][ni][3] * d1);
                *(__half2*)(g_Gh + (size_t)r1 * 128 + c) = h;
            }
        }
    }
}

// ---------------- GEMM: [NN x 128] @ [128 x 16] * dis[row] -> g_G16 (fp32) ------
__global__ __launch_bounds__(256) void gemm16_kernel(const float* __restrict__ W3)
{
    __shared__ float As[16][520];
    __shared__ float Bs[16][16];

    int tid = threadIdx.x;
    int m0  = blockIdx.x * 512;
    int tx  = tid & 1;
    int ty  = tid >> 1;

    float acc[4][8];
#pragma unroll
    for (int r = 0; r < 4; r++)
#pragma unroll
        for (int c = 0; c < 8; c++) acc[r][c] = 0.0f;

    for (int k0 = 0; k0 < 128; k0 += 16) {
#pragma unroll
        for (int i = 0; i < 8; i++) {
            int l   = i * 256 + tid;
            int row = l >> 2;
            int kc  = (l & 3) << 2;
            int gr  = m0 + row;
            float4 v = make_float4(0.f, 0.f, 0.f, 0.f);
            if (gr < NN) v = *(const float4*)(g_H + (size_t)gr * 128 + k0 + kc);
            As[kc + 0][row] = v.x;
            As[kc + 1][row] = v.y;
            As[kc + 2][row] = v.z;
            As[kc + 3][row] = v.w;
        }
        if (tid < 64) {
            int kr = tid >> 2;
            int nc = (tid & 3) << 2;
            *(float4*)&Bs[kr][nc] = *(const float4*)(W3 + (size_t)(k0 + kr) * 16 + nc);
        }
        __syncthreads();

#pragma unroll
        for (int k = 0; k < 16; k++) {
            float4 av = *(const float4*)&As[k][ty * 4];
            float a[4] = {av.x, av.y, av.z, av.w};
            float4 b0 = *(const float4*)&Bs[k][tx * 8];
            float4 b1 = *(const float4*)&Bs[k][tx * 8 + 4];
            float bb[8] = {b0.x,b0.y,b0.z,b0.w,b1.x,b1.y,b1.z,b1.w};
#pragma unroll
            for (int r = 0; r < 4; r++)
#pragma unroll
                for (int c = 0; c < 8; c++)
                    acc[r][c] += a[r] * bb[c];
        }
        __syncthreads();
    }

#pragma unroll
    for (int r = 0; r < 4; r++) {
        int gr = m0 + ty * 4 + r;
        if (gr < NN) {
            float d = g_dis[gr];
            float4 v0 = make_float4(acc[r][0]*d, acc[r][1]*d, acc[r][2]*d, acc[r][3]*d);
            float4 v1 = make_float4(acc[r][4]*d, acc[r][5]*d, acc[r][6]*d, acc[r][7]*d);
            *(float4*)(g_G16 + (size_t)gr * 16 + tx * 8)     = v0;
            *(float4*)(g_G16 + (size_t)gr * 16 + tx * 8 + 4) = v1;
        }
    }
}

// ---------------- Aggregation (128-wide, fp16 gather) ----------------
// scale_src=1 (layer 1): G unscaled -> H = relu(dis_i*(sum dis_s*G[s] + dis_i*G[i]) + b)
// scale_src=0 (layer 2): G pre-scaled -> H = relu(dis_i*(sum G[s] + G[i]) + b)
// One warp per node; lane l handles halfs [4l, 4l+4). 4x-unrolled edge loop.
__global__ __launch_bounds__(256) void agg128_kernel(const float* __restrict__ bias,
                                                     int scale_src)
{
    int gt   = blockIdx.x * blockDim.x + threadIdx.x;
    int node = gt >> 5;
    int lane = gt & 31;
    if (node >= NN) return;

    const uint2* __restrict__ Gv = (const uint2*)g_Gh;   // row = 32 uint2
    float d = g_dis[node];

    float4 acc = make_float4(0.f, 0.f, 0.f, 0.f);
    acc = h8_to_f4_sum(Gv[node * 32 + lane], scale_src ? d : 1.0f, acc);

    int j  = g_rowstart[node];
    int s1 = g_rowstart[node + 1];
    for (; j + 4 <= s1; j += 4) {
        int sa = g_csr[j],     sb = g_csr[j + 1];
        int sc = g_csr[j + 2], sd = g_csr[j + 3];
        uint2 va = Gv[sa * 32 + lane];
        uint2 vb = Gv[sb * 32 + lane];
        uint2 vc = Gv[sc * 32 + lane];
        uint2 vd = Gv[sd * 32 + lane];
        float wa = 1.0f, wb = 1.0f, wc = 1.0f, wd = 1.0f;
        if (scale_src) { wa = g_dis[sa]; wb = g_dis[sb]; wc = g_dis[sc]; wd = g_dis[sd]; }
        acc = h8_to_f4_sum(va, wa, acc);
        acc = h8_to_f4_sum(vb, wb, acc);
        acc = h8_to_f4_sum(vc, wc, acc);
        acc = h8_to_f4_sum(vd, wd, acc);
    }
    for (; j < s1; j++) {
        int s = g_csr[j];
        acc = h8_to_f4_sum(Gv[s * 32 + lane], scale_src ? g_dis[s] : 1.0f, acc);
    }

    float4 b = ((const float4*)bias)[lane];
    float4 r;
    r.x = fmaxf(acc.x * d + b.x, 0.0f);
    r.y = fmaxf(acc.y * d + b.y, 0.0f);
    r.z = fmaxf(acc.z * d + b.z, 0.0f);
    r.w = fmaxf(acc.w * d + b.w, 0.0f);
    ((float4*)g_H)[(size_t)node * 32 + lane] = r;
}

// ---------------- Aggregation (16-wide, final, fp32) ----------------
__global__ __launch_bounds__(256) void agg16_kernel(const float* __restrict__ bias,
                                                    float* __restrict__ out)
{
    int gt   = blockIdx.x * blockDim.x + threadIdx.x;
    int node = gt >> 2;
    int q    = gt & 3;
    if (node >= NN) return;

    const float4* __restrict__ Gv = (const float4*)g_G16;
    float4 acc = Gv[node * 4 + q];

    int j  = g_rowstart[node];
    int s1 = g_rowstart[node + 1];
    for (; j + 2 <= s1; j += 2) {
        int sa = g_csr[j], sb = g_csr[j + 1];
        float4 va = Gv[sa * 4 + q];
        float4 vb = Gv[sb * 4 + q];
        acc = f4add(acc, f4add(va, vb));
    }
    for (; j < s1; j++) acc = f4add(acc, Gv[g_csr[j] * 4 + q]);

    float d = g_dis[node];
    float4 b = ((const float4*)bias)[q];
    float4 r;
    r.x = acc.x * d + b.x;
    r.y = acc.y * d + b.y;
    r.z = acc.z * d + b.z;
    r.w = acc.w * d + b.w;
    ((float4*)out)[(size_t)node * 4 + q] = r;
}

// ---------------- launch ----------------
extern "C" void kernel_launch(void* const* d_in, const int* in_sizes, int n_in,
                              void* d_out, int out_size)
{
    const float* x  = (const float*)d_in[0];
    const void*  ei = d_in[1];                 // int32 or int64, detected on device
    const float* W1 = (const float*)d_in[2];
    const float* b1 = (const float*)d_in[3];
    const float* W2 = (const float*)d_in[4];
    const float* b2 = (const float*)d_in[5];
    const float* W3 = (const float*)d_in[6];
    const float* b3 = (const float*)d_in[7];
    float* out = (float*)d_out;

    // side stream + events (created once; host-side only, no device memory)
    static cudaStream_t s2 = nullptr;
    static cudaEvent_t  evFork = nullptr, evGemm = nullptr;
    if (!s2) {
        cudaStreamCreateWithFlags(&s2, cudaStreamNonBlocking);
        cudaEventCreateWithFlags(&evFork, cudaEventDisableTiming);
        cudaEventCreateWithFlags(&evGemm, cudaEventDisableTiming);
    }

    const int gemm_blocks   = (NN + 127) / 128;        // 391
    const int agg128_blocks = (NN * 32 + 255) / 256;   // 6250
    const int agg16_blocks  = (NN * 4 + 255) / 256;    // 782
    const int gemm16_blocks = (NN + 511) / 512;        // 98

    // Fork: GEMM-L1 (independent of preprocessing; dis deferred to agg)
    cudaEventRecord(evFork, 0);
    cudaStreamWaitEvent(s2, evFork, 0);
    gemm128_tc_kernel<<<gemm_blocks, 256, 0, s2>>>(x, W1, 256, 0, /*scale_dis=*/0);
    cudaEventRecord(evGemm, s2);

    // Main branch: preprocessing
    zero_deg_kernel<<<(NN + 255) / 256, 256>>>(ei);
    deg_kernel<<<(NE + 255) / 256, 256>>>(ei);
    scan_fused_kernel<<<SCAN_BLOCKS, 256>>>();
    fill_kernel<<<(NE + 255) / 256, 256>>>(ei);

    // Join, then layer 1 aggregation (applies dis on both sides)
    cudaStreamWaitEvent(0, evGemm, 0);
    agg128_kernel<<<agg128_blocks, 256>>>(b1, /*scale_src=*/1);

    // Layer 2 (dis in GEMM epilogue, as before)
    gemm128_tc_kernel<<<gemm_blocks, 256>>>(nullptr, W2, 128, 1, /*scale_dis=*/1);
    agg128_kernel<<<agg128_blocks, 256>>>(b2, /*scale_src=*/0);

    // Layer 3: 128 -> 16, no relu (fp32)
    gemm16_kernel<<<gemm16_blocks, 256>>>(W3);
    agg16_kernel<<<agg16_blocks, 256>>>(b3, out);
}